// round 6
// baseline (speedup 1.0000x reference)
#include <cuda_runtime.h>

#define LRELU(v) ((v) >= 0.f ? (v) : 0.01f*(v))

constexpr int B_=8, T_=60, S_=36, H_=4, E_=16, PE_=16, AD_=12, D_=28, TA_=10, C_=32, OH_=16;
constexpr int BH = B_*H_;         // 32
constexpr int SS = S_*S_;         // 1296
constexpr int KEEP = 648;         // floor(S*S*0.5)
constexpr float EPSf = 1e-5f;

// ---------------- device scratch ----------------
__device__ float g_pe[B_*T_*PE_];
__device__ float g_cnt[B_*S_];
__device__ float g_h[BH*T_*S_*E_];       // (b,h,t,s,e)
__device__ float g_alpha[BH*T_*SS];      // (b,h,t,s,j)  layer-1 only
__device__ float g_asum[BH*SS];          // t-sum of layer-1 alpha (atomic)
__device__ float g_adj[BH*SS];           // pruned adj
__device__ float g_bidir2[2*H_*SS];      // (lay,h,s,j)
__device__ float g_Hc[BH*S_*T_*C_];      // (b,h,s,t,d)
__device__ float g_beta[BH*S_*T_];       // (b,h,s,t)

__device__ __forceinline__ float blk_sum512(float v, float* sm){
  int tid = threadIdx.x;
  __syncthreads();
  sm[tid] = v; __syncthreads();
  #pragma unroll
  for(int s=256; s>0; s>>=1){ if(tid<s) sm[tid]+=sm[tid+s]; __syncthreads(); }
  return sm[0];
}

// ================= K0: prologue (BN+hinit | PE+cnt | bidir + zero asum) =================
__global__ void k_pro(const float* __restrict__ x, const float* __restrict__ bn_g,
                      const float* __restrict__ bn_b, const float* __restrict__ mask,
                      const float* __restrict__ times, const float* __restrict__ obs,
                      const float* __restrict__ bw){
  int blk = blockIdx.x, tid = threadIdx.x;
  if(blk < T_){
    __shared__ float sm[512];
    __shared__ float xn[B_*S_], mk[B_*S_];
    __shared__ float sc_, sh_;
    int t = blk;
    float v = 0.f;
    if(tid < B_*S_){ int b=tid/S_, s=tid%S_; v = x[(b*T_+t)*S_+s]; }
    float sum = blk_sum512(v, sm);
    float sq  = blk_sum512(v*v, sm);
    if(tid==0){
      float n=(float)(B_*S_);
      float mu=sum/n; float var=sq/n-mu*mu;
      sc_=bn_g[t]*rsqrtf(var+EPSf); sh_=bn_b[t]-mu*sc_;
    }
    __syncthreads();
    if(tid < B_*S_){
      int b=tid/S_, s=tid%S_;
      xn[tid]=v*sc_+sh_;
      mk[tid]=mask[(b*T_+t)*S_+s];
    }
    __syncthreads();
    for(int idx=tid; idx<B_*H_*S_*E_; idx+=512){
      int e  = idx & 15;
      int s  = (idx>>4)%S_;
      int hh = (idx/(16*S_))%H_;
      int b  = idx/(16*S_*H_);
      float val = xn[b*S_+s]*obs[s*(E_*H_)+hh*E_+e];
      val = LRELU(val);
      g_h[((b*H_+hh)*T_+t)*(S_*E_) + s*E_+e] = val*mk[b*S_+s];
    }
  } else if(blk == T_){
    for(int idx=tid; idx<B_*T_*PE_; idx+=512){
      int k=idx&15; int t=(idx>>4)%T_; int b=idx/(16*T_);
      float div = expf(-(float)(k>>1)*1.1512925464970229f);
      float ang = times[b*T_+t]*div;
      g_pe[idx] = (k&1) ? cosf(ang) : sinf(ang);
    }
    if(tid < B_*S_){
      int b=tid/S_, s=tid%S_;
      float c=0.f;
      #pragma unroll 4
      for(int t=0;t<T_;t++) c += mask[(b*T_+t)*S_+s];
      g_cnt[tid]=c;
    }
  } else {
    int gid = (blk - (T_+1))*512 + tid;
    for(int idx=gid; idx<2*H_*SS; idx+=8*512){
      int lay = idx/(H_*SS);
      int r   = idx%(H_*SS);
      int hh  = r/SS; int s=(r/S_)%S_; int j=r%S_;
      const float* w = bw + (size_t)(lay*H_+hh)*S_*AD_;
      float sum=0.f;
      #pragma unroll
      for(int d=0; d<AD_; d++) sum += w[s*AD_+d]*w[j*AD_+d];
      g_bidir2[idx]=LRELU(sum);
    }
    // zero g_asum (8 blocks x 512 threads cover 41472 floats)
    for(int idx=gid; idx<BH*SS; idx+=8*512) g_asum[idx]=0.f;
  }
}

// ================= K1: fused per-(b,h,t): hp -> alpha (-> msg if lay0; atomic asum if lay1) ====
__global__ void k_layer(const float* __restrict__ W, const float* __restrict__ pb,
                        const float* __restrict__ aw, int lay){
  __shared__ float sh_h[S_*E_];
  __shared__ float sh_hp[S_*D_];
  __shared__ float sh_W[D_*E_];
  __shared__ float sh_b[D_];
  __shared__ float sh_aw[S_*AD_];
  __shared__ float sh_pe[PE_];
  __shared__ float sh_C[S_];
  __shared__ float sh_a[SS];
  int blk = blockIdx.x, tid = threadIdx.x;
  int bh = blk/T_, t = blk%T_;
  int b = bh/H_, hh = bh%H_;
  int hbase = blk*S_*E_;
  for(int i=tid;i<S_*E_;i+=256) sh_h[i]=g_h[hbase+i];
  for(int i=tid;i<D_*E_;i+=256) sh_W[i]=W[i];
  if(tid<D_) sh_b[tid]=pb[tid];
  for(int i=tid;i<S_*AD_;i+=256) sh_aw[i]=aw[hh*S_*AD_+i];
  if(tid<PE_) sh_pe[tid]=g_pe[(b*T_+t)*PE_+tid];
  __syncthreads();
  // hp: padded (s,d) mapping, bit-indexed, d in [0,32) guarded to <28
  for(int o=tid;o<S_*32;o+=256){
    int s=o>>5, d=o&31;
    if(d<D_){
      float sum=sh_b[d];
      #pragma unroll
      for(int e=0;e<E_;e++) sum += sh_h[s*E_+e]*sh_W[d*E_+e];
      sh_hp[s*D_+d]=sum;
    }
  }
  __syncthreads();
  if(tid<S_){
    float c=0.f;
    #pragma unroll
    for(int d=0;d<PE_;d++) c += sh_hp[tid*D_+AD_+d]*sh_pe[d];
    sh_C[tid]=c;
  }
  __syncthreads();
  if(lay){
    int abase = blk*SS;
    int sbase = bh*SS;
    for(int o=tid;o<SS;o+=256){
      int s=o/S_, j=o-s*S_;
      float sum=sh_C[s];
      #pragma unroll
      for(int d=0;d<AD_;d++) sum += sh_hp[s*D_+d]*sh_aw[j*AD_+d];
      float a = LRELU(sum);
      g_alpha[abase+o]=a;
      atomicAdd(&g_asum[sbase+o], a);
    }
    return;
  }
  const float* bd = g_bidir2 + hh*SS;
  for(int o=tid;o<SS;o+=256){
    int s=o/S_, j=o-s*S_;
    float sum=sh_C[s];
    #pragma unroll
    for(int d=0;d<AD_;d++) sum += sh_hp[s*D_+d]*sh_aw[j*AD_+d];
    float a = LRELU(sum);
    sh_a[o] = LRELU(bd[o]*a);
  }
  __syncthreads();
  for(int o=tid;o<S_*E_;o+=256){
    int s=o>>4, e=o&15;
    float sum=0.f;
    #pragma unroll
    for(int j=0;j<S_;j++){
      float p = sh_h[j*E_+e]*sh_a[s*S_+j];
      sum += LRELU(p);
    }
    g_h[hbase+o]=LRELU(sum);
  }
}

// ================= K2: adj vals + prune, one 1024-thread block per (b,h) =================
__global__ void k_prune(){
  __shared__ float vals[SS];
  __shared__ float cnt[S_];
  int bh = blockIdx.x, tid = threadIdx.x;
  int b = bh/H_;
  if(tid<S_) cnt[tid]=g_cnt[b*S_+tid];
  __syncthreads();
  const float* src = g_asum + bh*SS;
  for(int i=tid;i<SS;i+=1024){
    int s=i/S_;
    vals[i]=LRELU(src[i]/cnt[s]);
  }
  __syncthreads();
  int wid = tid>>5, lane = tid&31;
  float* dst = g_adj + bh*SS;
  // warp w handles elements i = w, w+32, w+64, ... (41 per warp max)
  for(int i=wid; i<SS; i+=32){
    float v = vals[i];
    int c=0;
    for(int j=lane;j<SS;j+=32){
      float vj = vals[j];
      c += (vj<v) || (vj==v && j<i);
    }
    #pragma unroll
    for(int o=16;o>0;o>>=1) c += __shfl_xor_sync(0xffffffffu, c, o);
    if(lane==0) dst[i] = (c>=KEEP) ? v : 0.f;
  }
}

// ================= K3: layer-1 message passing per (b,h,t) =================
__global__ void k_msg1(){
  __shared__ float sh_h[S_*E_];
  __shared__ float sh_w[SS];
  int blk = blockIdx.x, tid = threadIdx.x;
  int bh = blk/T_; int hh = bh%H_;
  int hbase = blk*S_*E_;
  int abase = blk*SS;
  const float* bd = g_bidir2 + (H_+hh)*SS;
  const float* ad = g_adj + bh*SS;
  for(int i=tid;i<S_*E_;i+=256) sh_h[i]=g_h[hbase+i];
  for(int o=tid;o<SS;o+=256){
    float w = bd[o]*g_alpha[abase+o]*ad[o];
    sh_w[o]=LRELU(w);
  }
  __syncthreads();
  for(int o=tid;o<S_*E_;o+=256){
    int s=o>>4, e=o&15;
    float sum=0.f;
    #pragma unroll
    for(int j=0;j<S_;j++){
      float p = sh_h[j*E_+e]*sh_w[s*S_+j];
      sum += LRELU(p);
    }
    g_h[hbase+o]=LRELU(sum);
  }
}

// ================= K4: Hc + Q,K + collapsed beta, per (b,h,s) =================
__global__ void k_beta(const float* __restrict__ Wq, const float* __restrict__ bq,
                       const float* __restrict__ Wk, const float* __restrict__ bk,
                       const float* __restrict__ Ws, const float* __restrict__ bs){
  __shared__ float Hc[T_*C_];
  __shared__ float Qs[T_*TA_];
  __shared__ float Ks[T_*TA_];
  __shared__ float wq[TA_*C_], wk[TA_*C_];
  __shared__ float bqs[TA_], bks[TA_], wss[T_], kt[TA_];
  int blk = blockIdx.x;
  int bh = blk/S_, s = blk%S_;
  int b = bh/H_;
  int tid = threadIdx.x;
  for(int o=tid;o<T_*C_;o+=blockDim.x){
    int t=o>>5, d=o&31;
    float v = (d<E_) ? g_h[(bh*T_+t)*S_*E_ + s*E_ + d]
                     : g_pe[(b*T_+t)*PE_ + (d-E_)];
    Hc[o]=v;
    g_Hc[blk*T_*C_+o]=v;
  }
  for(int o=tid;o<TA_*C_;o+=blockDim.x){ wq[o]=Wq[o]; wk[o]=Wk[o]; }
  if(tid<TA_){ bqs[tid]=bq[tid]; bks[tid]=bk[tid]; }
  if(tid<T_) wss[tid]=Ws[tid];
  __syncthreads();
  for(int o=tid;o<T_*TA_;o+=blockDim.x){
    int t=o/TA_, q=o-t*TA_;
    float sq_=bqs[q], sk_=bks[q];
    #pragma unroll
    for(int d=0;d<C_;d++){ float hv=Hc[t*C_+d]; sq_+=hv*wq[q*C_+d]; sk_+=hv*wk[q*C_+d]; }
    Qs[o]=sq_; Ks[o]=sk_;
  }
  __syncthreads();
  if(tid<TA_){
    float sum=0.f;
    #pragma unroll
    for(int u=0;u<T_;u++) sum += wss[u]*Ks[u*TA_+tid];
    kt[tid]=sum;
  }
  __syncthreads();
  if(tid<T_){
    float sum = bs[0];
    #pragma unroll
    for(int q=0;q<TA_;q++) sum += Qs[tid*TA_+q]*kt[q];
    g_beta[blk*T_+tid]=sum;
  }
}

// ================= K5: epilogue per (b,h) =================
__global__ void k_final(const float* __restrict__ lnt_g, const float* __restrict__ lnt_b,
                        const float* __restrict__ Wse, const float* __restrict__ bse,
                        const float* __restrict__ lns_g, const float* __restrict__ lns_b,
                        float* __restrict__ out, int out_size){
  __shared__ float sm[512];
  __shared__ float bet[S_*T_];
  __shared__ float o1s[S_*C_];
  __shared__ float o2s[S_*OH_];
  __shared__ float mu_, rs_;
  int bh = blockIdx.x, tid = threadIdx.x;
  int b = bh/H_, hh = bh%H_;
  float s1=0.f, s2=0.f;
  for(int i=tid;i<S_*T_;i+=512){ float v=g_beta[bh*S_*T_+i]; bet[i]=v; s1+=v; s2+=v*v; }
  float sum = blk_sum512(s1, sm);
  float sq  = blk_sum512(s2, sm);
  if(tid==0){ float n=(float)(S_*T_); float mu=sum/n; float var=sq/n-mu*mu; mu_=mu; rs_=rsqrtf(var+EPSf); }
  __syncthreads();
  for(int i=tid;i<S_*T_;i+=512) bet[i]=(bet[i]-mu_)*rs_*lnt_g[i]+lnt_b[i];
  __syncthreads();
  for(int o=tid;o<S_*C_;o+=512){
    int s=o>>5, d=o&31;
    const float* hc = g_Hc + ((size_t)(bh*S_+s)*T_)*C_ + d;
    float sum2=0.f;
    #pragma unroll 4
    for(int t=0;t<T_;t++) sum2 += bet[s*T_+t]*hc[(size_t)t*C_];
    o1s[o]=LRELU(sum2);
  }
  __syncthreads();
  float t1=0.f, t2=0.f;
  for(int o=tid;o<S_*OH_;o+=512){
    int s=o/OH_, q=o&15;
    float sum2=bse[q];
    #pragma unroll
    for(int d=0;d<C_;d++) sum2 += o1s[s*C_+d]*Wse[q*C_+d];
    float v=LRELU(sum2);
    o2s[o]=v; t1+=v; t2+=v*v;
  }
  float sum2a = blk_sum512(t1, sm);
  float sq2a  = blk_sum512(t2, sm);
  if(tid==0){ float n=(float)(S_*OH_); float mu=sum2a/n; float var=sq2a/n-mu*mu; mu_=mu; rs_=rsqrtf(var+EPSf); }
  __syncthreads();
  for(int o=tid;o<S_*OH_;o+=512){
    int s=o/OH_, q=o&15;
    float v = (o2s[o]-mu_)*rs_*lns_g[o]+lns_b[o];
    out[(b*S_+s)*(H_*OH_) + hh*OH_ + q]=v;
  }
  if(bh==0){
    float qsum=0.f, tsum=0.f;
    for(int pos=tid; pos<H_*SS; pos+=512){
      int hhh=pos/SS, sj=pos%SS;
      float ts=0.f;
      #pragma unroll
      for(int bb=0;bb<B_;bb++){
        float v = g_adj[(bb*H_+hhh)*SS+sj];
        qsum += v*v; ts += v;
      }
      tsum += ts*ts;
    }
    float Sq = blk_sum512(qsum, sm);
    float T2 = blk_sum512(tsum, sm);
    if(tid==0 && out_size > B_*S_*H_*OH_)
      out[B_*S_*H_*OH_] = ((float)B_*Sq - T2) / (float)((B_-1)*(B_-1)) / (float)SS;
  }
}

// ---------------- launcher ----------------
extern "C" void kernel_launch(void* const* d_in, const int* in_sizes, int n_in,
                              void* d_out, int out_size){
  const float* x      = (const float*)d_in[0];
  const float* times  = (const float*)d_in[1];
  const float* mask   = (const float*)d_in[2];
  const float* bn_g   = (const float*)d_in[3];
  const float* bn_b   = (const float*)d_in[4];
  const float* obs    = (const float*)d_in[5];
  const float* attn_w = (const float*)d_in[6];
  const float* bidir_w= (const float*)d_in[7];
  const float* proj_W = (const float*)d_in[8];
  const float* proj_b = (const float*)d_in[9];
  const float* Wq     = (const float*)d_in[10];
  const float* bq     = (const float*)d_in[11];
  const float* Wk     = (const float*)d_in[12];
  const float* bk     = (const float*)d_in[13];
  const float* Ws     = (const float*)d_in[14];
  const float* bs     = (const float*)d_in[15];
  const float* lnt_g  = (const float*)d_in[16];
  const float* lnt_b  = (const float*)d_in[17];
  const float* Wse    = (const float*)d_in[18];
  const float* bse    = (const float*)d_in[19];
  const float* lns_g  = (const float*)d_in[20];
  const float* lns_b  = (const float*)d_in[21];
  float* out = (float*)d_out;

  k_pro<<<T_+1+8, 512>>>(x, bn_g, bn_b, mask, times, obs, bidir_w);
  k_layer<<<BH*T_, 256>>>(proj_W, proj_b, attn_w, 0);
  k_layer<<<BH*T_, 256>>>(proj_W, proj_b, attn_w + (size_t)H_*S_*AD_, 1);
  k_prune<<<BH, 1024>>>();
  k_msg1<<<BH*T_, 256>>>();
  k_beta<<<BH*S_, 256>>>(Wq, bq, Wk, bk, Ws, bs);
  k_final<<<BH, 512>>>(lnt_g, lnt_b, Wse, bse, lns_g, lns_b, out, out_size);
}

// round 7
// speedup vs baseline: 1.1988x; 1.1988x over previous
#include <cuda_runtime.h>

#define LRELU(v) ((v) >= 0.f ? (v) : 0.01f*(v))

constexpr int B_=8, T_=60, S_=36, H_=4, E_=16, PE_=16, AD_=12, D_=28, TA_=10, C_=32, OH_=16;
constexpr int BH = B_*H_;         // 32
constexpr int SS = S_*S_;         // 1296
constexpr int KEEP = 648;         // floor(S*S*0.5)
constexpr float EPSf = 1e-5f;

// ---------------- device scratch ----------------
__device__ float g_pe[B_*T_*PE_];
__device__ float g_cnt[B_*S_];
__device__ float g_h[BH*T_*S_*E_];       // (b,h,t,s,e)
__device__ float g_alpha[BH*T_*SS];      // (b,h,t,s,j)  layer-1 only
__device__ float g_asum[BH*SS];          // t-sum of layer-1 alpha (atomic)
__device__ float g_adj[BH*SS];           // pruned adj
__device__ float g_bidir2[2*H_*SS];      // (lay,h,s,j)
__device__ float g_Hc[BH*S_*T_*C_];      // (b,h,s,t,d)
__device__ float g_beta[BH*S_*T_];       // (b,h,s,t)

__device__ __forceinline__ float blk_sum512(float v, float* sm){
  int tid = threadIdx.x;
  __syncthreads();
  sm[tid] = v; __syncthreads();
  #pragma unroll
  for(int s=256; s>0; s>>=1){ if(tid<s) sm[tid]+=sm[tid+s]; __syncthreads(); }
  return sm[0];
}

// ================= K0: prologue (BN+hinit | PE+cnt | bidir + zero asum) =================
__global__ void k_pro(const float* __restrict__ x, const float* __restrict__ bn_g,
                      const float* __restrict__ bn_b, const float* __restrict__ mask,
                      const float* __restrict__ times, const float* __restrict__ obs,
                      const float* __restrict__ bw){
  int blk = blockIdx.x, tid = threadIdx.x;
  if(blk < T_){
    __shared__ float sm[512];
    __shared__ float xn[B_*S_], mk[B_*S_];
    __shared__ float sc_, sh_;
    int t = blk;
    float v = 0.f;
    if(tid < B_*S_){ int b=tid/S_, s=tid%S_; v = x[(b*T_+t)*S_+s]; }
    float sum = blk_sum512(v, sm);
    float sq  = blk_sum512(v*v, sm);
    if(tid==0){
      float n=(float)(B_*S_);
      float mu=sum/n; float var=sq/n-mu*mu;
      sc_=bn_g[t]*rsqrtf(var+EPSf); sh_=bn_b[t]-mu*sc_;
    }
    __syncthreads();
    if(tid < B_*S_){
      int b=tid/S_, s=tid%S_;
      xn[tid]=v*sc_+sh_;
      mk[tid]=mask[(b*T_+t)*S_+s];
    }
    __syncthreads();
    for(int idx=tid; idx<B_*H_*S_*E_; idx+=512){
      int e  = idx & 15;
      int s  = (idx>>4)%S_;
      int hh = (idx/(16*S_))%H_;
      int b  = idx/(16*S_*H_);
      float val = xn[b*S_+s]*obs[s*(E_*H_)+hh*E_+e];
      val = LRELU(val);
      g_h[((b*H_+hh)*T_+t)*(S_*E_) + s*E_+e] = val*mk[b*S_+s];
    }
  } else if(blk == T_){
    for(int idx=tid; idx<B_*T_*PE_; idx+=512){
      int k=idx&15; int t=(idx>>4)%T_; int b=idx/(16*T_);
      float div = expf(-(float)(k>>1)*1.1512925464970229f);
      float ang = times[b*T_+t]*div;
      g_pe[idx] = (k&1) ? cosf(ang) : sinf(ang);
    }
    if(tid < B_*S_){
      int b=tid/S_, s=tid%S_;
      float c=0.f;
      #pragma unroll 4
      for(int t=0;t<T_;t++) c += mask[(b*T_+t)*S_+s];
      g_cnt[tid]=c;
    }
  } else {
    int gid = (blk - (T_+1))*512 + tid;
    for(int idx=gid; idx<2*H_*SS; idx+=8*512){
      int lay = idx/(H_*SS);
      int r   = idx%(H_*SS);
      int hh  = r/SS; int s=(r/S_)%S_; int j=r%S_;
      const float* w = bw + (size_t)(lay*H_+hh)*S_*AD_;
      float sum=0.f;
      #pragma unroll
      for(int d=0; d<AD_; d++) sum += w[s*AD_+d]*w[j*AD_+d];
      g_bidir2[idx]=LRELU(sum);
    }
    // zero g_asum (8 blocks x 512 threads cover 41472 floats)
    for(int idx=gid; idx<BH*SS; idx+=8*512) g_asum[idx]=0.f;
  }
}

// ================= K1: fused per-(b,h,t): hp -> alpha (-> msg if lay0; atomic asum if lay1) ====
__global__ void k_layer(const float* __restrict__ W, const float* __restrict__ pb,
                        const float* __restrict__ aw, int lay){
  __shared__ float sh_h[S_*E_];
  __shared__ float sh_hp[S_*D_];
  __shared__ float sh_W[D_*E_];
  __shared__ float sh_b[D_];
  __shared__ float sh_aw[S_*AD_];
  __shared__ float sh_pe[PE_];
  __shared__ float sh_C[S_];
  __shared__ float sh_a[SS];
  int blk = blockIdx.x, tid = threadIdx.x;
  int bh = blk/T_, t = blk%T_;
  int b = bh/H_, hh = bh%H_;
  int hbase = blk*S_*E_;
  for(int i=tid;i<S_*E_;i+=256) sh_h[i]=g_h[hbase+i];
  for(int i=tid;i<D_*E_;i+=256) sh_W[i]=W[i];
  if(tid<D_) sh_b[tid]=pb[tid];
  for(int i=tid;i<S_*AD_;i+=256) sh_aw[i]=aw[hh*S_*AD_+i];
  if(tid<PE_) sh_pe[tid]=g_pe[(b*T_+t)*PE_+tid];
  __syncthreads();
  for(int o=tid;o<S_*32;o+=256){
    int s=o>>5, d=o&31;
    if(d<D_){
      float sum=sh_b[d];
      #pragma unroll
      for(int e=0;e<E_;e++) sum += sh_h[s*E_+e]*sh_W[d*E_+e];
      sh_hp[s*D_+d]=sum;
    }
  }
  __syncthreads();
  if(tid<S_){
    float c=0.f;
    #pragma unroll
    for(int d=0;d<PE_;d++) c += sh_hp[tid*D_+AD_+d]*sh_pe[d];
    sh_C[tid]=c;
  }
  __syncthreads();
  if(lay){
    int abase = blk*SS;
    int sbase = bh*SS;
    for(int o=tid;o<SS;o+=256){
      int s=o/S_, j=o-s*S_;
      float sum=sh_C[s];
      #pragma unroll
      for(int d=0;d<AD_;d++) sum += sh_hp[s*D_+d]*sh_aw[j*AD_+d];
      float a = LRELU(sum);
      g_alpha[abase+o]=a;
      atomicAdd(&g_asum[sbase+o], a);
    }
    return;
  }
  const float* bd = g_bidir2 + hh*SS;
  for(int o=tid;o<SS;o+=256){
    int s=o/S_, j=o-s*S_;
    float sum=sh_C[s];
    #pragma unroll
    for(int d=0;d<AD_;d++) sum += sh_hp[s*D_+d]*sh_aw[j*AD_+d];
    float a = LRELU(sum);
    sh_a[o] = LRELU(bd[o]*a);
  }
  __syncthreads();
  for(int o=tid;o<S_*E_;o+=256){
    int s=o>>4, e=o&15;
    float sum=0.f;
    #pragma unroll
    for(int j=0;j<S_;j++){
      float p = sh_h[j*E_+e]*sh_a[s*S_+j];
      sum += LRELU(p);
    }
    g_h[hbase+o]=LRELU(sum);
  }
}

// ================= K2: prune, wide — one block per (b,h,row): grid=BH*36 =================
__global__ void k_prune(){
  __shared__ float vals[SS];
  __shared__ float cnt[S_];
  int bh = blockIdx.x/S_;
  int row = blockIdx.x%S_;
  int tid = threadIdx.x;
  int b = bh/H_;
  if(tid<S_) cnt[tid]=g_cnt[b*S_+tid];
  __syncthreads();
  const float* src = g_asum + bh*SS;
  for(int i=tid;i<SS;i+=256){
    int s=i/S_;
    vals[i]=LRELU(src[i]/cnt[s]);
  }
  __syncthreads();
  int wid = tid>>5, lane = tid&31;
  float* dst = g_adj + bh*SS;
  // 8 warps cover the 36 elements of this row
  for(int e=wid; e<S_; e+=8){
    int i = row*S_ + e;
    float v = vals[i];
    int c=0;
    for(int j=lane;j<SS;j+=32){
      float vj = vals[j];
      c += (vj<v) || (vj==v && j<i);
    }
    #pragma unroll
    for(int o=16;o>0;o>>=1) c += __shfl_xor_sync(0xffffffffu, c, o);
    if(lane==0) dst[i] = (c>=KEEP) ? v : 0.f;
  }
}

// ================= K3: layer-1 message passing per (b,h,t) =================
__global__ void k_msg1(){
  __shared__ float sh_h[S_*E_];
  __shared__ float sh_w[SS];
  int blk = blockIdx.x, tid = threadIdx.x;
  int bh = blk/T_; int hh = bh%H_;
  int hbase = blk*S_*E_;
  int abase = blk*SS;
  const float* bd = g_bidir2 + (H_+hh)*SS;
  const float* ad = g_adj + bh*SS;
  for(int i=tid;i<S_*E_;i+=256) sh_h[i]=g_h[hbase+i];
  for(int o=tid;o<SS;o+=256){
    float w = bd[o]*g_alpha[abase+o]*ad[o];
    sh_w[o]=LRELU(w);
  }
  __syncthreads();
  for(int o=tid;o<S_*E_;o+=256){
    int s=o>>4, e=o&15;
    float sum=0.f;
    #pragma unroll
    for(int j=0;j<S_;j++){
      float p = sh_h[j*E_+e]*sh_w[s*S_+j];
      sum += LRELU(p);
    }
    g_h[hbase+o]=LRELU(sum);
  }
}

// ================= K4: Hc + Q,K + collapsed beta, per (b,h,s) =================
__global__ void k_beta(const float* __restrict__ Wq, const float* __restrict__ bq,
                       const float* __restrict__ Wk, const float* __restrict__ bk,
                       const float* __restrict__ Ws, const float* __restrict__ bs){
  __shared__ float Hc[T_*C_];
  __shared__ float Qs[T_*TA_];
  __shared__ float Ks[T_*TA_];
  __shared__ float wq[TA_*C_], wk[TA_*C_];
  __shared__ float bqs[TA_], bks[TA_], wss[T_], kt[TA_];
  int blk = blockIdx.x;
  int bh = blk/S_, s = blk%S_;
  int b = bh/H_;
  int tid = threadIdx.x;
  for(int o=tid;o<T_*C_;o+=blockDim.x){
    int t=o>>5, d=o&31;
    float v = (d<E_) ? g_h[(bh*T_+t)*S_*E_ + s*E_ + d]
                     : g_pe[(b*T_+t)*PE_ + (d-E_)];
    Hc[o]=v;
    g_Hc[blk*T_*C_+o]=v;
  }
  for(int o=tid;o<TA_*C_;o+=blockDim.x){ wq[o]=Wq[o]; wk[o]=Wk[o]; }
  if(tid<TA_){ bqs[tid]=bq[tid]; bks[tid]=bk[tid]; }
  if(tid<T_) wss[tid]=Ws[tid];
  __syncthreads();
  for(int o=tid;o<T_*TA_;o+=blockDim.x){
    int t=o/TA_, q=o-t*TA_;
    float sq_=bqs[q], sk_=bks[q];
    #pragma unroll
    for(int d=0;d<C_;d++){ float hv=Hc[t*C_+d]; sq_+=hv*wq[q*C_+d]; sk_+=hv*wk[q*C_+d]; }
    Qs[o]=sq_; Ks[o]=sk_;
  }
  __syncthreads();
  if(tid<TA_){
    float sum=0.f;
    #pragma unroll
    for(int u=0;u<T_;u++) sum += wss[u]*Ks[u*TA_+tid];
    kt[tid]=sum;
  }
  __syncthreads();
  if(tid<T_){
    float sum = bs[0];
    #pragma unroll
    for(int q=0;q<TA_;q++) sum += Qs[tid*TA_+q]*kt[q];
    g_beta[blk*T_+tid]=sum;
  }
}

// ================= K5: epilogue per (b,h) =================
__global__ void k_final(const float* __restrict__ lnt_g, const float* __restrict__ lnt_b,
                        const float* __restrict__ Wse, const float* __restrict__ bse,
                        const float* __restrict__ lns_g, const float* __restrict__ lns_b,
                        float* __restrict__ out, int out_size){
  __shared__ float sm[512];
  __shared__ float bet[S_*T_];
  __shared__ float o1s[S_*C_];
  __shared__ float o2s[S_*OH_];
  __shared__ float mu_, rs_;
  int bh = blockIdx.x, tid = threadIdx.x;
  int b = bh/H_, hh = bh%H_;
  float s1=0.f, s2=0.f;
  for(int i=tid;i<S_*T_;i+=512){ float v=g_beta[bh*S_*T_+i]; bet[i]=v; s1+=v; s2+=v*v; }
  float sum = blk_sum512(s1, sm);
  float sq  = blk_sum512(s2, sm);
  if(tid==0){ float n=(float)(S_*T_); float mu=sum/n; float var=sq/n-mu*mu; mu_=mu; rs_=rsqrtf(var+EPSf); }
  __syncthreads();
  for(int i=tid;i<S_*T_;i+=512) bet[i]=(bet[i]-mu_)*rs_*lnt_g[i]+lnt_b[i];
  __syncthreads();
  for(int o=tid;o<S_*C_;o+=512){
    int s=o>>5, d=o&31;
    const float* hc = g_Hc + ((size_t)(bh*S_+s)*T_)*C_ + d;
    float sum2=0.f;
    #pragma unroll 4
    for(int t=0;t<T_;t++) sum2 += bet[s*T_+t]*hc[(size_t)t*C_];
    o1s[o]=LRELU(sum2);
  }
  __syncthreads();
  float t1=0.f, t2=0.f;
  for(int o=tid;o<S_*OH_;o+=512){
    int s=o/OH_, q=o&15;
    float sum2=bse[q];
    #pragma unroll
    for(int d=0;d<C_;d++) sum2 += o1s[s*C_+d]*Wse[q*C_+d];
    float v=LRELU(sum2);
    o2s[o]=v; t1+=v; t2+=v*v;
  }
  float sum2a = blk_sum512(t1, sm);
  float sq2a  = blk_sum512(t2, sm);
  if(tid==0){ float n=(float)(S_*OH_); float mu=sum2a/n; float var=sq2a/n-mu*mu; mu_=mu; rs_=rsqrtf(var+EPSf); }
  __syncthreads();
  for(int o=tid;o<S_*OH_;o+=512){
    int s=o/OH_, q=o&15;
    float v = (o2s[o]-mu_)*rs_*lns_g[o]+lns_b[o];
    out[(b*S_+s)*(H_*OH_) + hh*OH_ + q]=v;
  }
  if(bh==0){
    float qsum=0.f, tsum=0.f;
    for(int pos=tid; pos<H_*SS; pos+=512){
      int hhh=pos/SS, sj=pos%SS;
      float ts=0.f;
      #pragma unroll
      for(int bb=0;bb<B_;bb++){
        float v = g_adj[(bb*H_+hhh)*SS+sj];
        qsum += v*v; ts += v;
      }
      tsum += ts*ts;
    }
    float Sq = blk_sum512(qsum, sm);
    float T2 = blk_sum512(tsum, sm);
    if(tid==0 && out_size > B_*S_*H_*OH_)
      out[B_*S_*H_*OH_] = ((float)B_*Sq - T2) / (float)((B_-1)*(B_-1)) / (float)SS;
  }
}

// ---------------- launcher ----------------
extern "C" void kernel_launch(void* const* d_in, const int* in_sizes, int n_in,
                              void* d_out, int out_size){
  const float* x      = (const float*)d_in[0];
  const float* times  = (const float*)d_in[1];
  const float* mask   = (const float*)d_in[2];
  const float* bn_g   = (const float*)d_in[3];
  const float* bn_b   = (const float*)d_in[4];
  const float* obs    = (const float*)d_in[5];
  const float* attn_w = (const float*)d_in[6];
  const float* bidir_w= (const float*)d_in[7];
  const float* proj_W = (const float*)d_in[8];
  const float* proj_b = (const float*)d_in[9];
  const float* Wq     = (const float*)d_in[10];
  const float* bq     = (const float*)d_in[11];
  const float* Wk     = (const float*)d_in[12];
  const float* bk     = (const float*)d_in[13];
  const float* Ws     = (const float*)d_in[14];
  const float* bs     = (const float*)d_in[15];
  const float* lnt_g  = (const float*)d_in[16];
  const float* lnt_b  = (const float*)d_in[17];
  const float* Wse    = (const float*)d_in[18];
  const float* bse    = (const float*)d_in[19];
  const float* lns_g  = (const float*)d_in[20];
  const float* lns_b  = (const float*)d_in[21];
  float* out = (float*)d_out;

  k_pro<<<T_+1+8, 512>>>(x, bn_g, bn_b, mask, times, obs, bidir_w);
  k_layer<<<BH*T_, 256>>>(proj_W, proj_b, attn_w, 0);
  k_layer<<<BH*T_, 256>>>(proj_W, proj_b, attn_w + (size_t)H_*S_*AD_, 1);
  k_prune<<<BH*S_, 256>>>();
  k_msg1<<<BH*T_, 256>>>();
  k_beta<<<BH*S_, 256>>>(Wq, bq, Wk, bk, Ws, bs);
  k_final<<<BH, 512>>>(lnt_g, lnt_b, Wse, bse, lns_g, lns_b, out, out_size);
}